// round 2
// baseline (speedup 1.0000x reference)
#include <cuda_runtime.h>
#include <math.h>

#define BB 16
#define NN 128
#define DD 64
#define BN  2048        // BB*NN
#define BND 131072      // BN*DD
#define BNDD 8388608    // BND*DD

// out layout (tuple order): prediction[BND], target[BND], A_new[BN*NN], W1n[BNDD], W2n[BNDD], W3n[BNDD]
#define OFF_T  (BND)
#define OFF_A  (2*BND)
#define OFF_W1 (4*BND)            // 2*BND + BN*NN = 4*BND
#define OFF_W2 (OFF_W1 + BNDD)
#define OFF_W3 (OFF_W2 + BNDD)

// scratch (static device globals; no allocation)
__device__ float g_q[BND];
__device__ float g_k[BND];
__device__ float g_coef[BND];
__device__ float g_noisy[BND];
__device__ float g_mag[BB];
__device__ float g_pe[BB];
__device__ float g_pe2[BB];
__device__ float g_std;

__device__ __forceinline__ float wredMax(float v) {
    #pragma unroll
    for (int o = 16; o; o >>= 1) v = fmaxf(v, __shfl_xor_sync(0xffffffffu, v, o));
    return v;
}
__device__ __forceinline__ float wredSum(float v) {
    #pragma unroll
    for (int o = 16; o; o >>= 1) v += __shfl_xor_sync(0xffffffffu, v, o);
    return v;
}

// ---------------------------------------------------------------------------
// K1: per (b,n) three matvecs: raw_pred = state@W1, k = state@W2, q = state@W3
// plus prediction elementwise. 2048 blocks x 192 threads.
// ---------------------------------------------------------------------------
__global__ void __launch_bounds__(192) k1_qkp(
    const float* __restrict__ state,
    const float* __restrict__ W1, const float* __restrict__ W2, const float* __restrict__ W3,
    float* __restrict__ out)
{
    int bn = blockIdx.x;
    int t  = threadIdx.x;
    int x  = t >> 6;          // 0: W1(pred), 1: W2(k), 2: W3(q)
    int kk = t & 63;

    __shared__ float s[DD];
    if (t < DD) s[t] = state[bn * DD + t];
    __syncthreads();

    const float* Wp = (x == 0) ? W1 : ((x == 1) ? W2 : W3);
    const float* Wb = Wp + (size_t)bn * DD * DD + kk;
    float acc = 0.f;
    #pragma unroll
    for (int j = 0; j < DD; j++) acc += s[j] * Wb[j * DD];

    if (x == 0) {
        float raw = acc - tanhf(acc) * 0.6f;
        out[bn * DD + kk] = tanhf(raw) * 1.8477590650225735f;  // sqrt(2+sqrt(2))
    } else if (x == 1) {
        g_k[bn * DD + kk] = acc;
    } else {
        g_q[bn * DD + kk] = acc;
    }
}

// ---------------------------------------------------------------------------
// K2: attention row per block: raw_A, dense softmax, keep-mask, renorm P,
// A_new (rows 0,1 zeroed), target = A_new @ output with env clamp.
// 2048 blocks x 128 threads.
// ---------------------------------------------------------------------------
__global__ void __launch_bounds__(128) k2_attn(
    const float* __restrict__ A,
    const float* __restrict__ noiseA,
    const float* __restrict__ outputv,
    const float* __restrict__ eye,
    const float* __restrict__ stomach,
    float* __restrict__ out)
{
    int bn = blockIdx.x;
    int b  = bn >> 7;
    int n  = bn & 127;
    int m  = threadIdx.x;

    if (n < 2) {
        out[OFF_A + (size_t)bn * NN + m] = 0.f;
        if (m < DD) out[OFF_T + bn * DD + m] = (n == 0) ? eye[b * DD + m] : stomach[b * DD + m];
        return;
    }

    __shared__ float qs[DD];
    __shared__ float red[4];
    __shared__ float anew[NN];

    if (m < DD) qs[m] = g_q[bn * DD + m];
    __syncthreads();

    const float4* krow = (const float4*)(g_k + (size_t)(b * NN + m) * DD);
    float dot = 0.f;
    #pragma unroll
    for (int i = 0; i < DD / 4; i++) {
        float4 v = krow[i];
        dot += qs[4*i] * v.x + qs[4*i+1] * v.y + qs[4*i+2] * v.z + qs[4*i+3] * v.w;
    }
    float raw = dot * 0.125f + noiseA[(size_t)bn * NN + m] * 1e-5f;

    // row max
    float v = wredMax(raw);
    if ((m & 31) == 0) red[m >> 5] = v;
    __syncthreads();
    float rowmax = fmaxf(fmaxf(red[0], red[1]), fmaxf(red[2], red[3]));
    __syncthreads();

    float e = expf(raw - rowmax);
    v = wredSum(e);
    if ((m & 31) == 0) red[m >> 5] = v;
    __syncthreads();
    float sum = red[0] + red[1] + red[2] + red[3];
    __syncthreads();

    float pd = e / sum;
    v = wredMax(pd);
    if ((m & 31) == 0) red[m >> 5] = v;
    __syncthreads();
    float maxpd = fmaxf(fmaxf(red[0], red[1]), fmaxf(red[2], red[3]));
    __syncthreads();

    bool keep = (pd > (1.0f / 129.0f)) || (pd == maxpd);
    float ek = keep ? e : 0.f;
    v = wredSum(ek);
    if ((m & 31) == 0) red[m >> 5] = v;
    __syncthreads();
    float sum2 = red[0] + red[1] + red[2] + red[3];
    __syncthreads();

    float P  = ek / sum2;
    float an = A[(size_t)bn * NN + m] * 0.99f + P * 0.01f;
    out[OFF_A + (size_t)bn * NN + m] = an;
    anew[m] = an;
    __syncthreads();

    if (m < DD) {
        float acc = 0.f;
        #pragma unroll 8
        for (int mm = 0; mm < NN; mm++)
            acc += anew[mm] * outputv[(size_t)(b * NN + mm) * DD + m];
        out[OFF_T + bn * DD + m] = acc;
    }
}

// ---------------------------------------------------------------------------
// K3: per-b state magnitude + per-b partial err sums. 16 blocks x 512 threads.
// ---------------------------------------------------------------------------
__global__ void __launch_bounds__(512) k3_stats(
    const float* __restrict__ state, const float* __restrict__ out)
{
    int b = blockIdx.x;
    int t = threadIdx.x;
    float am = 0.f, ae = 0.f, ae2 = 0.f;
    #pragma unroll 4
    for (int idx = t; idx < NN * DD; idx += 512) {
        int g = b * NN * DD + idx;
        am += fabsf(state[g]);
        float e = out[g] - out[OFF_T + g];
        ae += e; ae2 += e * e;
    }
    am = wredSum(am); ae = wredSum(ae); ae2 = wredSum(ae2);
    __shared__ float s0[16], s1[16], s2[16];
    int w = t >> 5;
    if ((t & 31) == 0) { s0[w] = am; s1[w] = ae; s2[w] = ae2; }
    __syncthreads();
    if (t < 32) {
        float a  = (t < 16) ? s0[t] : 0.f;
        float bb = (t < 16) ? s1[t] : 0.f;
        float c  = (t < 16) ? s2[t] : 0.f;
        a = wredSum(a); bb = wredSum(bb); c = wredSum(c);
        if (t == 0) { g_mag[b] = a; g_pe[b] = bb; g_pe2[b] = c; }
    }
}

// K3b: final std(err, ddof=1). 1 block x 32 threads.
__global__ void k3b_std()
{
    int t = threadIdx.x;
    float e  = (t < BB) ? g_pe[t]  : 0.f;
    float e2 = (t < BB) ? g_pe2[t] : 0.f;
    e = wredSum(e); e2 = wredSum(e2);
    if (t == 0) {
        const float M = (float)BND;
        float var = (e2 - e * e / M) / (M - 1.0f);
        g_std = sqrtf(fmaxf(var, 0.f));
    }
}

// ---------------------------------------------------------------------------
// K4: per (b,n): E_curr softmax over D, Eb EMA, plasticity/mask, noisy_state,
// outer-product rms factorization -> coef, noisy. 2048 blocks x 64 threads.
// ---------------------------------------------------------------------------
__global__ void __launch_bounds__(64) k4_coef(
    const float* __restrict__ state,
    const float* __restrict__ Ebase,
    const float* __restrict__ n1raw,
    const float* __restrict__ n2raw,
    const float* __restrict__ out)
{
    int bn = blockIdx.x;
    int b  = bn >> 7;
    int i  = threadIdx.x;
    int g  = bn * DD + i;

    __shared__ float red[2];
    float err = out[g] - out[OFF_T + g];

    // softmax(err) over D (64 threads = 2 warps)
    float v = wredMax(err);
    if ((i & 31) == 0) red[i >> 5] = v;
    __syncthreads();
    float mx = fmaxf(red[0], red[1]);
    __syncthreads();
    float ex = expf(err - mx);
    v = wredSum(ex);
    if ((i & 31) == 0) red[i >> 5] = v;
    __syncthreads();
    float sm = red[0] + red[1];
    __syncthreads();
    float Ec = ex / sm;

    float Eb0 = Ebase[g];
    float Eb  = (Eb0 == 0.f) ? Ec : Eb0;       // bmask blend
    Eb = Eb * 0.95f + 0.05f * Ec;
    float adv   = Ec - Eb;
    float plast = 1.f + adv * rsqrtf(adv * adv + 1e-6f);   // 1 - R
    float mk    = (Eb > 0.f) ? 1.f : 0.f;

    float ns = state[g] + n1raw[g] / (1.f + g_mag[b]) + n2raw[g] * g_std * 0.8f;

    v = wredSum(err * err);
    if ((i & 31) == 0) red[i >> 5] = v;
    __syncthreads();
    float se2 = red[0] + red[1];
    __syncthreads();
    v = wredSum(ns * ns);
    if ((i & 31) == 0) red[i >> 5] = v;
    __syncthreads();
    float sn2 = red[0] + red[1];

    float rn = rsqrtf((se2 * (1.f / DD)) * (sn2 * (1.f / DD)) + 1e-6f);
    g_coef[g]  = -err * rn * plast * mk;
    g_noisy[g] = ns;
}

// ---------------------------------------------------------------------------
// K5: fused grads + momentum + gaussian column mask + W update + row rms.
// 16 threads per row (float4 each), 16 rows per 256-thread block.
// ---------------------------------------------------------------------------
__device__ __forceinline__ float newW(float w, float wlat, float m, float h, float g) {
    float grad = h + 0.01f * wlat - 0.01f * w;     // LAT_DECAY*W_lat - WD*W_self
    return w + 0.0033f * (m * 0.4f + 0.6f * grad * g);
}

__global__ void __launch_bounds__(256) k5_update(
    const float* __restrict__ W1, const float* __restrict__ W2, const float* __restrict__ W3,
    const float* __restrict__ M1, const float* __restrict__ M2, const float* __restrict__ M3,
    const int* __restrict__ stepc,
    float* __restrict__ out)
{
    int t   = threadIdx.x;
    int tx  = t & 15;
    int row = blockIdx.x * 16 + (t >> 4);  // 0..BND-1  (b,n,i)
    int bn  = row >> 6;
    size_t b4 = (size_t)row * 16 + tx;     // float4 index into (BND x D) matrices

    float4 w1 = ((const float4*)W1)[b4];
    float4 w2 = ((const float4*)W2)[b4];
    float4 w3 = ((const float4*)W3)[b4];
    float4 m1 = ((const float4*)M1)[b4];
    float4 m2 = ((const float4*)M2)[b4];
    float4 m3 = ((const float4*)M3)[b4];

    float  c  = g_coef[row];
    float4 ns = ((const float4*)g_noisy)[bn * 16 + tx];

    float scf    = (float)(*stepc) + 1.0f;
    float center = fmodf(scf * 0.5f, 64.0f);
    int j0 = tx * 4;
    float4 gm;
    {
        float d;
        d = fabsf((float)(j0 + 0) - center); d = fminf(d, 64.f - d); gm.x = expf(-d * d / 0.020001f);
        d = fabsf((float)(j0 + 1) - center); d = fminf(d, 64.f - d); gm.y = expf(-d * d / 0.020001f);
        d = fabsf((float)(j0 + 2) - center); d = fminf(d, 64.f - d); gm.z = expf(-d * d / 0.020001f);
        d = fabsf((float)(j0 + 3) - center); d = fminf(d, 64.f - d); gm.w = expf(-d * d / 0.020001f);
    }

    float4 t1, t2, t3;
    t1.x = newW(w1.x, w3.x, m1.x, c * ns.x, gm.x);
    t1.y = newW(w1.y, w3.y, m1.y, c * ns.y, gm.y);
    t1.z = newW(w1.z, w3.z, m1.z, c * ns.z, gm.z);
    t1.w = newW(w1.w, w3.w, m1.w, c * ns.w, gm.w);
    t2.x = newW(w2.x, w1.x, m2.x, c * ns.x, gm.x);
    t2.y = newW(w2.y, w1.y, m2.y, c * ns.y, gm.y);
    t2.z = newW(w2.z, w1.z, m2.z, c * ns.z, gm.z);
    t2.w = newW(w2.w, w1.w, m2.w, c * ns.w, gm.w);
    t3.x = newW(w3.x, w2.x, m3.x, c * ns.x, gm.x);
    t3.y = newW(w3.y, w2.y, m3.y, c * ns.y, gm.y);
    t3.z = newW(w3.z, w2.z, m3.z, c * ns.z, gm.z);
    t3.w = newW(w3.w, w2.w, m3.w, c * ns.w, gm.w);

    float s1 = t1.x*t1.x + t1.y*t1.y + t1.z*t1.z + t1.w*t1.w;
    float s2 = t2.x*t2.x + t2.y*t2.y + t2.z*t2.z + t2.w*t2.w;
    float s3 = t3.x*t3.x + t3.y*t3.y + t3.z*t3.z + t3.w*t3.w;
    #pragma unroll
    for (int o = 8; o; o >>= 1) {
        s1 += __shfl_xor_sync(0xffffffffu, s1, o);
        s2 += __shfl_xor_sync(0xffffffffu, s2, o);
        s3 += __shfl_xor_sync(0xffffffffu, s3, o);
    }
    float r1 = rsqrtf(s1 * (1.f / 64.f) + 1e-6f);
    float r2 = rsqrtf(s2 * (1.f / 64.f) + 1e-6f);
    float r3 = rsqrtf(s3 * (1.f / 64.f) + 1e-6f);

    float4 o1 = { t1.x*r1, t1.y*r1, t1.z*r1, t1.w*r1 };
    float4 o2 = { t2.x*r2, t2.y*r2, t2.z*r2, t2.w*r2 };
    float4 o3 = { t3.x*r3, t3.y*r3, t3.z*r3, t3.w*r3 };
    ((float4*)(out + OFF_W1))[b4] = o1;
    ((float4*)(out + OFF_W2))[b4] = o2;
    ((float4*)(out + OFF_W3))[b4] = o3;
}

// ---------------------------------------------------------------------------
extern "C" void kernel_launch(void* const* d_in, const int* in_sizes, int n_in,
                              void* d_out, int out_size)
{
    const float* eye     = (const float*)d_in[0];
    const float* stomach = (const float*)d_in[1];
    const float* state   = (const float*)d_in[2];
    const float* outputv = (const float*)d_in[3];
    const float* W1      = (const float*)d_in[4];
    const float* W2      = (const float*)d_in[5];
    const float* W3      = (const float*)d_in[6];
    const float* M1      = (const float*)d_in[7];
    const float* M2      = (const float*)d_in[8];
    const float* M3      = (const float*)d_in[9];
    const float* Ebase   = (const float*)d_in[10];
    const float* A       = (const float*)d_in[11];
    const float* noiseA  = (const float*)d_in[12];
    const float* n1raw   = (const float*)d_in[13];
    const float* n2raw   = (const float*)d_in[14];
    const int*   stepc   = (const int*)d_in[15];
    float* out = (float*)d_out;

    k1_qkp<<<BN, 192>>>(state, W1, W2, W3, out);
    k2_attn<<<BN, 128>>>(A, noiseA, outputv, eye, stomach, out);
    k3_stats<<<BB, 512>>>(state, out);
    k3b_std<<<1, 32>>>();
    k4_coef<<<BN, DD>>>(state, Ebase, n1raw, n2raw, out);
    k5_update<<<BND / 16, 256>>>(W1, W2, W3, M1, M2, M3, stepc, out);
}